// round 2
// baseline (speedup 1.0000x reference)
#include <cuda_runtime.h>

#define B_    128
#define T_    128
#define N_    128
#define M_    256
#define FourM 1024

// Scratch (device globals: no allocation allowed in kernel_launch)
__device__ float g_XWx[(size_t)B_ * T_ * FourM];   // [b*T + t][j]  : x_t@Wx + b   (64 MB)
__device__ float g_UXt[(size_t)B_ * T_ * N_];      // [b][u][n]     : U(X^T) + bU  (8 MB)

__device__ __forceinline__ float sigmoid_(float x) {
    return __fdividef(1.f, 1.f + __expf(-x));
}
// Accurate-enough fast tanh: 1 - 2/(e^{2x}+1). Handles +-inf limits correctly.
__device__ __forceinline__ float tanh_(float x) {
    float e = __expf(2.f * x);
    return 1.f - __fdividef(2.f, e + 1.f);
}

// ---------------------------------------------------------------------------
// Kernel 1: g_XWx[bt][j] = sum_n X[bt][n] * Wx[n][j] + b[j]
// Plain register-tiled fp32 SGEMM: 64x64 block tile, 4x4 per thread, K=128.
// ---------------------------------------------------------------------------
__global__ void __launch_bounds__(256) xwx_gemm(const float* __restrict__ X,
                                                const float* __restrict__ Wx,
                                                const float* __restrict__ bias) {
    __shared__ float As[16][64];   // As[k][m]
    __shared__ float Bs[16][64];   // Bs[k][j]
    const int tid  = threadIdx.x;
    const int row0 = blockIdx.y * 64;
    const int col0 = blockIdx.x * 64;
    const int tx = tid & 15;
    const int ty = tid >> 4;
    const int am = tid >> 2;
    const int ak = (tid & 3) * 4;
    const int bk = tid >> 4;
    const int bj = (tid & 15) * 4;

    float acc[4][4];
#pragma unroll
    for (int i = 0; i < 4; i++)
#pragma unroll
        for (int j = 0; j < 4; j++) acc[i][j] = 0.f;

    for (int k0 = 0; k0 < 128; k0 += 16) {
        float4 av = *(const float4*)(X + (row0 + am) * 128 + k0 + ak);
        As[ak + 0][am] = av.x;
        As[ak + 1][am] = av.y;
        As[ak + 2][am] = av.z;
        As[ak + 3][am] = av.w;
        *(float4*)&Bs[bk][bj] = *(const float4*)(Wx + (k0 + bk) * FourM + col0 + bj);
        __syncthreads();
#pragma unroll
        for (int k = 0; k < 16; k++) {
            float4 a4 = *(const float4*)&As[k][ty * 4];
            float4 b4 = *(const float4*)&Bs[k][tx * 4];
            float a[4] = {a4.x, a4.y, a4.z, a4.w};
            float b[4] = {b4.x, b4.y, b4.z, b4.w};
#pragma unroll
            for (int i = 0; i < 4; i++)
#pragma unroll
                for (int j = 0; j < 4; j++) acc[i][j] = fmaf(a[i], b[j], acc[i][j]);
        }
        __syncthreads();
    }
    float4 b4 = *(const float4*)(bias + col0 + tx * 4);
    float bb[4] = {b4.x, b4.y, b4.z, b4.w};
#pragma unroll
    for (int i = 0; i < 4; i++) {
        float4 r = make_float4(acc[i][0] + bb[0], acc[i][1] + bb[1],
                               acc[i][2] + bb[2], acc[i][3] + bb[3]);
        *(float4*)&g_XWx[(row0 + ty * 4 + i) * FourM + col0 + tx * 4] = r;
    }
}

// ---------------------------------------------------------------------------
// Kernel 2: g_UXt[b][u][n] = sum_t X[b][t][n] * Ud[t][u] + bU[u]
// One CTA per batch; X/Ud staged through smem in 32-row chunks.
// ---------------------------------------------------------------------------
__global__ void __launch_bounds__(256) uxt_kernel(const float* __restrict__ X,
                                                  const float* __restrict__ Ud,
                                                  const float* __restrict__ bU) {
    __shared__ float Xs[32][128];
    __shared__ float Us[32][128];
    const int b   = blockIdx.x;
    const int tid = threadIdx.x;
    const int n   = tid & 127;
    const int uh  = tid >> 7;   // 0/1 : which half of u-range

    float acc[64];
#pragma unroll
    for (int i = 0; i < 64; ++i) acc[i] = 0.f;

    for (int t0 = 0; t0 < 128; t0 += 32) {
        for (int l = tid; l < 32 * 128; l += 256) {
            int tt = l >> 7, nn = l & 127;
            Xs[tt][nn] = X[(b * 128 + t0 + tt) * 128 + nn];
            Us[tt][nn] = Ud[(t0 + tt) * 128 + nn];
        }
        __syncthreads();
#pragma unroll 2
        for (int tt = 0; tt < 32; ++tt) {
            float xv = Xs[tt][n];
            const float* up = &Us[tt][uh * 64];
#pragma unroll
            for (int uu = 0; uu < 64; ++uu) acc[uu] = fmaf(xv, up[uu], acc[uu]);
        }
        __syncthreads();
    }
#pragma unroll 4
    for (int uu = 0; uu < 64; ++uu) {
        int u = uh * 64 + uu;
        g_UXt[(b * 128 + u) * 128 + n] = acc[uu] + bU[u];
    }
}

// ---------------------------------------------------------------------------
// Kernel 3: the recurrence + attention. One CTA owns 2 batch elements for all
// 128 timesteps — everything CTA-local, no grid sync. 512 threads.
// All global loads are LDG.128 to stay off the LDG issue floor.
// ---------------------------------------------------------------------------
__global__ void __launch_bounds__(512, 1) darnn_main(
    const float* __restrict__ X,
    const float* __restrict__ h0,
    const float* __restrict__ s0,
    const float* __restrict__ Wh,   // [256][1024]
    const float* __restrict__ Wd,   // [512][128]
    const float* __restrict__ bW,   // [128]
    const float* __restrict__ vd,   // [128]
    float* __restrict__ out) {
    __shared__ float hsm[2][M_];
    __shared__ float csm[2][M_];
    __shared__ float zs[2][4][M_];
    __shared__ float wsm[2][T_];
    __shared__ float esm[2][N_];
    __shared__ float part[512 * 4];
    __shared__ float vds[T_];
    __shared__ float bWs[T_];
    __shared__ float redmax[2][4];
    __shared__ float redsum[2][4];

    const int tid = threadIdx.x;
    const int b0  = blockIdx.x * 2;

    {
        int b = tid >> 8, m = tid & 255;
        hsm[b][m] = h0[(b0 + b) * M_ + m];
        csm[b][m] = s0[(b0 + b) * M_ + m];
    }
    if (tid < T_) { vds[tid] = vd[tid]; bWs[tid] = bW[tid]; }
    __syncthreads();

    // phase-1 mapping: thread = (batch-half, gate, 4 consecutive m). Warp has
    // consecutive mg -> each gate load is a 512B-contiguous LDG.128 burst.
    const int p1_b  = tid >> 8;
    const int p1_g  = (tid >> 6) & 3;
    const int p1_mg = tid & 63;
    const float* whp0 = Wh + p1_g * M_ + p1_mg * 4;   // + k*1024 per row

    // phase-2 mapping: warp-uniform k-range (broadcast LDS of hs), consecutive ug.
    const int p2_b  = tid >> 8;
    const int p2_kq = (tid >> 5) & 7;
    const int p2_ug = tid & 31;

    // phase-3 mapping: warp-uniform u-range, consecutive ng.
    const int p3_b  = tid >> 8;
    const int p3_uq = (tid >> 5) & 7;
    const int p3_ng = tid & 31;

    for (int t = 0; t < T_; ++t) {
        // ---------- phase 1: z = XWx[b,t] + h @ Wh ----------
        {
            const float* xw = g_XWx + ((b0 + p1_b) * T_ + t) * FourM + p1_g * M_ + p1_mg * 4;
            float4 a = *(const float4*)xw;
            float acc0 = a.x, acc1 = a.y, acc2 = a.z, acc3 = a.w;
            const float* wp = whp0;
            const float* hv = hsm[p1_b];
#pragma unroll 8
            for (int k = 0; k < M_; ++k) {
                float h  = hv[k];
                float4 w4 = *(const float4*)wp;
                wp += FourM;
                acc0 = fmaf(h, w4.x, acc0);
                acc1 = fmaf(h, w4.y, acc1);
                acc2 = fmaf(h, w4.z, acc2);
                acc3 = fmaf(h, w4.w, acc3);
            }
            *(float4*)&zs[p1_b][p1_g][p1_mg * 4] = make_float4(acc0, acc1, acc2, acc3);
        }
        __syncthreads();
        // ---------- gates / state update: thread = (b, m) ----------
        {
            int b = tid >> 8, m = tid & 255;
            float ig = sigmoid_(zs[b][0][m]);
            float fg = sigmoid_(zs[b][1][m]);
            float gg = tanh_(zs[b][2][m]);
            float og = sigmoid_(zs[b][3][m]);
            float c  = fmaf(fg, csm[b][m], ig * gg);
            float h  = og * tanh_(c);
            csm[b][m] = c;
            hsm[b][m] = h;
        }
        __syncthreads();
        // ---------- phase 2: w = [h;c] @ Wd + bW  (k-split partials) ----------
        {
            float a0 = 0, a1 = 0, a2 = 0, a3 = 0;
            const int kbase = p2_kq * 64;
            const float* wdp = Wd + p2_ug * 4;
#pragma unroll 8
            for (int kk = 0; kk < 64; ++kk) {
                int k = kbase + kk;
                float hv = (k < M_) ? hsm[p2_b][k] : csm[p2_b][k - M_];
                float4 w4 = *(const float4*)(wdp + k * T_);
                a0 = fmaf(hv, w4.x, a0);
                a1 = fmaf(hv, w4.y, a1);
                a2 = fmaf(hv, w4.z, a2);
                a3 = fmaf(hv, w4.w, a3);
            }
            *(float4*)&part[tid * 4] = make_float4(a0, a1, a2, a3);
        }
        __syncthreads();
        if (tid < 256) {
            int b = tid >> 7, u = tid & 127;
            int ug = u >> 2, ui = u & 3;
            float s = bWs[u];
#pragma unroll
            for (int kq = 0; kq < 8; ++kq)
                s += part[((b << 8) + kq * 32 + ug) * 4 + ui];
            wsm[b][u] = s;
        }
        __syncthreads();
        // ---------- phase 3: e[b,n] = sum_u tanh(w[u] + UXt[b,u,n]) * vd[u] ----------
        {
            float a0 = 0, a1 = 0, a2 = 0, a3 = 0;
            const int ubase = p3_uq * 16;
            const float* uxp = g_UXt + (b0 + p3_b) * (T_ * N_) + p3_ng * 4;
#pragma unroll 4
            for (int uu = 0; uu < 16; ++uu) {
                int u = ubase + uu;
                float wv = wsm[p3_b][u];
                float vv = vds[u];
                float4 x4 = *(const float4*)(uxp + u * N_);
                a0 = fmaf(tanh_(wv + x4.x), vv, a0);
                a1 = fmaf(tanh_(wv + x4.y), vv, a1);
                a2 = fmaf(tanh_(wv + x4.z), vv, a2);
                a3 = fmaf(tanh_(wv + x4.w), vv, a3);
            }
            *(float4*)&part[tid * 4] = make_float4(a0, a1, a2, a3);
        }
        __syncthreads();
        if (tid < 256) {
            int b = tid >> 7, n = tid & 127;
            int ng = n >> 2, ni = n & 3;
            float e = 0.f;
#pragma unroll
            for (int uq = 0; uq < 8; ++uq)
                e += part[((b << 8) + uq * 32 + ng) * 4 + ni];
            esm[b][n] = e;
        }
        __syncthreads();
        // ---------- softmax over n (per batch = 4 warps) + write output ----------
        float p_reg = 0.f;
        if (tid < 256) {
            int b = tid >> 7, n = tid & 127;
            float mx = esm[b][n];
#pragma unroll
            for (int off = 16; off; off >>= 1)
                mx = fmaxf(mx, __shfl_xor_sync(0xffffffffu, mx, off));
            if ((n & 31) == 0) redmax[b][n >> 5] = mx;
        }
        __syncthreads();
        if (tid < 256) {
            int b = tid >> 7, n = tid & 127;
            float mx = fmaxf(fmaxf(redmax[b][0], redmax[b][1]),
                             fmaxf(redmax[b][2], redmax[b][3]));
            p_reg = __expf(esm[b][n] - mx);
            float s = p_reg;
#pragma unroll
            for (int off = 16; off; off >>= 1)
                s += __shfl_xor_sync(0xffffffffu, s, off);
            if ((n & 31) == 0) redsum[b][n >> 5] = s;
        }
        __syncthreads();
        if (tid < 256) {
            int b = tid >> 7, n = tid & 127;
            float tot   = redsum[b][0] + redsum[b][1] + redsum[b][2] + redsum[b][3];
            float alpha = __fdividef(p_reg, tot);
            int idx = ((b0 + b) * T_ + t) * N_ + n;
            out[idx] = X[idx] * alpha;
        }
        // no trailing sync needed: every smem buffer written next iteration is
        // separated from its last reader here by at least one __syncthreads.
    }
}

// ---------------------------------------------------------------------------
// Inputs (metadata order): X, h0, s0, Wx, Wh, b, Wd, bW, Ud, bU, vd, bv.
// bv is a constant shift inside the softmax -> cancels exactly; unused.
// ---------------------------------------------------------------------------
extern "C" void kernel_launch(void* const* d_in, const int* in_sizes, int n_in,
                              void* d_out, int out_size) {
    const float* X  = (const float*)d_in[0];
    const float* h0 = (const float*)d_in[1];
    const float* s0 = (const float*)d_in[2];
    const float* Wx = (const float*)d_in[3];
    const float* Wh = (const float*)d_in[4];
    const float* bz = (const float*)d_in[5];
    const float* Wd = (const float*)d_in[6];
    const float* bW = (const float*)d_in[7];
    const float* Ud = (const float*)d_in[8];
    const float* bU = (const float*)d_in[9];
    const float* vd = (const float*)d_in[10];
    float* out = (float*)d_out;

    dim3 g1(FourM / 64, (B_ * T_) / 64);     // (16, 256)
    xwx_gemm<<<g1, 256>>>(X, Wx, bz);
    uxt_kernel<<<B_, 256>>>(X, Ud, bU);
    darnn_main<<<B_ / 2, 512>>>(X, h0, s0, Wh, Wd, bW, vd, out);
}

// round 4
// speedup vs baseline: 1.3180x; 1.3180x over previous
#include <cuda_runtime.h>
#include <cstdint>

#define B_    128
#define T_    128
#define N_    128
#define M_    256
#define FourM 1024
#define RANKS 8     // CTAs per cluster; CTA r owns m-slice [r*32,(r+1)*32)
#define MB    8     // batches per cluster

// Scratch (device globals: no allocation allowed)
__device__ float g_XWx[(size_t)B_ * T_ * FourM];   // [b*T + t][j] : x@Wx + b
__device__ float g_UXt[(size_t)B_ * T_ * N_];      // [b][u][n]    : U(X^T) + bU

__device__ __forceinline__ float sigmoid_(float x) {
    return __fdividef(1.f, 1.f + __expf(-x));
}
__device__ __forceinline__ float tanh_(float x) {          // accurate (gates)
    float e = __expf(2.f * x);
    return 1.f - __fdividef(2.f, e + 1.f);
}
__device__ __forceinline__ float tanha_(float x) {         // fast (attention)
    float y;
    asm("tanh.approx.f32 %0, %1;" : "=f"(y) : "f"(x));
    return y;
}
__device__ __forceinline__ uint32_t smem_u32(const void* p) {
    return (uint32_t)__cvta_generic_to_shared(p);
}
__device__ __forceinline__ uint32_t mapa_rank(uint32_t a, uint32_t r) {
    uint32_t d;
    asm("mapa.shared::cluster.u32 %0, %1, %2;" : "=r"(d) : "r"(a), "r"(r));
    return d;
}
__device__ __forceinline__ void st_cluster4(uint32_t a, float4 v) {
    asm volatile("st.shared::cluster.v4.f32 [%0], {%1,%2,%3,%4};"
                 :: "r"(a), "f"(v.x), "f"(v.y), "f"(v.z), "f"(v.w) : "memory");
}
__device__ __forceinline__ void cluster_sync_() {
    asm volatile("barrier.cluster.arrive.aligned;" ::: "memory");
    asm volatile("barrier.cluster.wait.aligned;" ::: "memory");
}

// ---------------------------------------------------------------------------
// Kernel 1: g_XWx = X @ Wx + b
// ---------------------------------------------------------------------------
__global__ void __launch_bounds__(256) xwx_gemm(const float* __restrict__ X,
                                                const float* __restrict__ Wx,
                                                const float* __restrict__ bias) {
    __shared__ float As[16][64];
    __shared__ float Bs[16][64];
    const int tid  = threadIdx.x;
    const int row0 = blockIdx.y * 64;
    const int col0 = blockIdx.x * 64;
    const int tx = tid & 15;
    const int ty = tid >> 4;
    const int am = tid >> 2;
    const int ak = (tid & 3) * 4;
    const int bk = tid >> 4;
    const int bj = (tid & 15) * 4;

    float acc[4][4];
#pragma unroll
    for (int i = 0; i < 4; i++)
#pragma unroll
        for (int j = 0; j < 4; j++) acc[i][j] = 0.f;

    for (int k0 = 0; k0 < 128; k0 += 16) {
        float4 av = *(const float4*)(X + (row0 + am) * 128 + k0 + ak);
        As[ak + 0][am] = av.x;
        As[ak + 1][am] = av.y;
        As[ak + 2][am] = av.z;
        As[ak + 3][am] = av.w;
        *(float4*)&Bs[bk][bj] = *(const float4*)(Wx + (k0 + bk) * FourM + col0 + bj);
        __syncthreads();
#pragma unroll
        for (int k = 0; k < 16; k++) {
            float4 a4 = *(const float4*)&As[k][ty * 4];
            float4 b4 = *(const float4*)&Bs[k][tx * 4];
            float a[4] = {a4.x, a4.y, a4.z, a4.w};
            float b[4] = {b4.x, b4.y, b4.z, b4.w};
#pragma unroll
            for (int i = 0; i < 4; i++)
#pragma unroll
                for (int j = 0; j < 4; j++) acc[i][j] = fmaf(a[i], b[j], acc[i][j]);
        }
        __syncthreads();
    }
    float4 b4 = *(const float4*)(bias + col0 + tx * 4);
    float bb[4] = {b4.x, b4.y, b4.z, b4.w};
#pragma unroll
    for (int i = 0; i < 4; i++) {
        float4 rr = make_float4(acc[i][0] + bb[0], acc[i][1] + bb[1],
                                acc[i][2] + bb[2], acc[i][3] + bb[3]);
        *(float4*)&g_XWx[(size_t)(row0 + ty * 4 + i) * FourM + col0 + tx * 4] = rr;
    }
}

// ---------------------------------------------------------------------------
// Kernel 2: g_UXt[b][u][n] = sum_t X[b][t][n]*Ud[t][u] + bU[u]
// ---------------------------------------------------------------------------
__global__ void __launch_bounds__(256) uxt_kernel(const float* __restrict__ X,
                                                  const float* __restrict__ Ud,
                                                  const float* __restrict__ bU) {
    __shared__ float Xs[32][128];
    __shared__ float Us[32][128];
    const int b   = blockIdx.x;
    const int tid = threadIdx.x;
    const int n   = tid & 127;
    const int uh  = tid >> 7;

    float acc[64];
#pragma unroll
    for (int i = 0; i < 64; ++i) acc[i] = 0.f;

    for (int t0 = 0; t0 < 128; t0 += 32) {
        for (int l = tid; l < 32 * 128; l += 256) {
            int tt = l >> 7, nn = l & 127;
            Xs[tt][nn] = X[(b * 128 + t0 + tt) * 128 + nn];
            Us[tt][nn] = Ud[(t0 + tt) * 128 + nn];
        }
        __syncthreads();
#pragma unroll 2
        for (int tt = 0; tt < 32; ++tt) {
            float xv = Xs[tt][n];
            const float* up = &Us[tt][uh * 64];
#pragma unroll
            for (int uu = 0; uu < 64; ++uu) acc[uu] = fmaf(xv, up[uu], acc[uu]);
        }
        __syncthreads();
    }
#pragma unroll 4
    for (int uu = 0; uu < 64; ++uu) {
        int u = uh * 64 + uu;
        g_UXt[(size_t)(b * 128 + u) * 128 + n] = acc[uu] + bU[u];
    }
}

// ---------------------------------------------------------------------------
// Kernel 3: 16 clusters x 8 CTAs. Wh/Wd slices smem-resident; DSMEM h gather.
// ---------------------------------------------------------------------------
struct SM {
    float Whs[256][128];     // [k][j]  j = g*32+mi -> global col g*256+r*32+mi
    float Wds[64][128];      // [kk][u] kk<32: h rows r*32+kk ; kk>=32: c rows
    float h_all[8][256];     // gathered h for the cluster's 8 batches
    float zbuf[2][8][32][4]; // p1 k-split partials [ks][b][quad][4]
    float zfull[8][128];     // z for local columns
    float hs_own[8][64];     // [b][0:32)=h slice, [32:64)=c slice (this step)
    float c_loc[8][32];      // persistent c for own m-slice
    float wrecv[8][128];     // w partials from each src rank (for MY batch)
    float wsm[128];
    float epart[8][128];
    float vds[128];
    float bWs[128];
    float redm[4];
    float reds[4];
};

__global__ void __launch_bounds__(256, 1) __cluster_dims__(RANKS, 1, 1)
darnn_main(const float* __restrict__ X, const float* __restrict__ h0,
           const float* __restrict__ s0, const float* __restrict__ Wh,
           const float* __restrict__ Wd, const float* __restrict__ bW,
           const float* __restrict__ vd, float* __restrict__ out) {
    extern __shared__ char smraw[];
    SM& s = *reinterpret_cast<SM*>(smraw);
    const int tid = threadIdx.x;
    const int r   = blockIdx.x & 7;            // rank in cluster
    const int b0  = (blockIdx.x >> 3) * MB;    // cluster's global batch base
    const int gb  = b0 + r;                    // batch this CTA owns (attention)

    // ---- prologue: resident weights + state ----
    for (int fid = tid; fid < 256 * 32; fid += 256) {
        int k = fid >> 5, jq = fid & 31;
        int g = jq >> 3, mi4 = (jq & 7) * 4;
        *(float4*)&s.Whs[k][jq * 4] =
            *(const float4*)(Wh + (size_t)k * FourM + g * 256 + r * 32 + mi4);
    }
    for (int fid = tid; fid < 64 * 32; fid += 256) {
        int kk = fid >> 5, uq4 = (fid & 31) * 4;
        int gk = (kk < 32) ? (r * 32 + kk) : (256 + r * 32 + (kk - 32));
        *(float4*)&s.Wds[kk][uq4] = *(const float4*)(Wd + (size_t)gk * T_ + uq4);
    }
    for (int fid = tid; fid < 8 * 64; fid += 256) {
        int b = fid >> 6, k4 = (fid & 63) * 4;
        *(float4*)&s.h_all[b][k4] = *(const float4*)(h0 + (size_t)(b0 + b) * M_ + k4);
    }
    {
        int b = tid >> 5, mi = tid & 31;
        s.c_loc[b][mi] = s0[(size_t)(b0 + b) * M_ + r * 32 + mi];
    }
    if (tid < 128) { s.vds[tid] = vd[tid]; s.bWs[tid] = bW[tid]; }
    __syncthreads();

    // thread mappings
    const int p_bl = tid & 3;          // batch pair (bl*2, bl*2+1)
    const int p_q  = (tid >> 2) & 31;  // column quad
    const int p_ks = tid >> 7;         // k half
    const int rb   = tid >> 5;         // (b) for reduce/gates
    const int rq   = tid & 31;         // (quad / mi)
    const int g_g  = rq >> 3;          // xwx gate decode for quad rq
    const int g_m4 = (rq & 7) * 4;
    const int w_ul = tid >> 3;         // wpart u-quad
    const int w_bw = tid & 7;          // wpart batch
    const int e_ng = tid & 31;         // p3 n-quad
    const int e_uq = tid >> 5;         // p3 u-range

    for (int t = 0; t < T_; ++t) {
        // XWx prefetch for reduce thread (rb, rq)
        float4 xw4 = *(const float4*)(g_XWx + ((size_t)(b0 + rb) * T_ + t) * FourM
                                      + g_g * 256 + r * 32 + g_m4);
        // ---- phase 1: z-partials over a k-half, 2 batches x 4 cols ----
        float aA[4] = {0, 0, 0, 0}, aB[4] = {0, 0, 0, 0};
        {
            const float* hA = s.h_all[p_bl * 2];
            const float* hB = s.h_all[p_bl * 2 + 1];
#pragma unroll 4
            for (int kt = 0; kt < 32; ++kt) {
                int k = p_ks * 128 + kt * 4;
                float4 ha = *(const float4*)(hA + k);
                float4 hb = *(const float4*)(hB + k);
                float4 w0 = *(const float4*)&s.Whs[k + 0][p_q * 4];
                float4 w1 = *(const float4*)&s.Whs[k + 1][p_q * 4];
                float4 w2 = *(const float4*)&s.Whs[k + 2][p_q * 4];
                float4 w3 = *(const float4*)&s.Whs[k + 3][p_q * 4];
                aA[0] = fmaf(ha.x, w0.x, fmaf(ha.y, w1.x, fmaf(ha.z, w2.x, fmaf(ha.w, w3.x, aA[0]))));
                aA[1] = fmaf(ha.x, w0.y, fmaf(ha.y, w1.y, fmaf(ha.z, w2.y, fmaf(ha.w, w3.y, aA[1]))));
                aA[2] = fmaf(ha.x, w0.z, fmaf(ha.y, w1.z, fmaf(ha.z, w2.z, fmaf(ha.w, w3.z, aA[2]))));
                aA[3] = fmaf(ha.x, w0.w, fmaf(ha.y, w1.w, fmaf(ha.z, w2.w, fmaf(ha.w, w3.w, aA[3]))));
                aB[0] = fmaf(hb.x, w0.x, fmaf(hb.y, w1.x, fmaf(hb.z, w2.x, fmaf(hb.w, w3.x, aB[0]))));
                aB[1] = fmaf(hb.x, w0.y, fmaf(hb.y, w1.y, fmaf(hb.z, w2.y, fmaf(hb.w, w3.y, aB[1]))));
                aB[2] = fmaf(hb.x, w0.z, fmaf(hb.y, w1.z, fmaf(hb.z, w2.z, fmaf(hb.w, w3.z, aB[2]))));
                aB[3] = fmaf(hb.x, w0.w, fmaf(hb.y, w1.w, fmaf(hb.z, w2.w, fmaf(hb.w, w3.w, aB[3]))));
            }
        }
        *(float4*)s.zbuf[p_ks][p_bl * 2 + 0][p_q] = make_float4(aA[0], aA[1], aA[2], aA[3]);
        *(float4*)s.zbuf[p_ks][p_bl * 2 + 1][p_q] = make_float4(aB[0], aB[1], aB[2], aB[3]);

        cluster_sync_();   // #1: all peers done reading h_all; zbuf visible locally

        // ---- z reduce ----
        {
            float4 u0 = *(const float4*)s.zbuf[0][rb][rq];
            float4 u1 = *(const float4*)s.zbuf[1][rb][rq];
            *(float4*)&s.zfull[rb][rq * 4] =
                make_float4(xw4.x + u0.x + u1.x, xw4.y + u0.y + u1.y,
                            xw4.z + u0.z + u1.z, xw4.w + u0.w + u1.w);
        }
        __syncthreads();
        // ---- gates for own m-slice: (rb, rq) = (b, mi) ----
        {
            float ig = sigmoid_(s.zfull[rb][rq]);
            float fg = sigmoid_(s.zfull[rb][32 + rq]);
            float gg = tanh_(s.zfull[rb][64 + rq]);
            float og = sigmoid_(s.zfull[rb][96 + rq]);
            float c  = fmaf(fg, s.c_loc[rb][rq], ig * gg);
            float h  = og * tanh_(c);
            s.c_loc[rb][rq]       = c;
            s.hs_own[rb][rq]      = h;
            s.hs_own[rb][32 + rq] = c;
        }
        __syncthreads();
        // ---- h broadcast to all ranks (64 threads) ----
        if (tid < 64) {
            int b = tid >> 3, qm = tid & 7;
            float4 h4  = *(const float4*)&s.hs_own[b][qm * 4];
            uint32_t la = smem_u32(&s.h_all[b][r * 32 + qm * 4]);
#pragma unroll
            for (int d = 0; d < 8; ++d) st_cluster4(mapa_rank(la, d), h4);
        }
        // ---- w partial over own k-slice, pushed to batch owner ----
        {
            float a[4] = {0, 0, 0, 0};
            const float* hp = s.hs_own[w_bw];
#pragma unroll 8
            for (int kk = 0; kk < 64; ++kk) {
                float hv  = hp[kk];
                float4 w4 = *(const float4*)&s.Wds[kk][w_ul * 4];
                a[0] = fmaf(hv, w4.x, a[0]);
                a[1] = fmaf(hv, w4.y, a[1]);
                a[2] = fmaf(hv, w4.z, a[2]);
                a[3] = fmaf(hv, w4.w, a[3]);
            }
            uint32_t la = smem_u32(&s.wrecv[r][w_ul * 4]);
            st_cluster4(mapa_rank(la, w_bw), make_float4(a[0], a[1], a[2], a[3]));
        }

        cluster_sync_();   // #2: h_all updated + w partials delivered

        // ---- combine w ----
        if (tid < 128) {
            float wv = s.bWs[tid];
#pragma unroll
            for (int src = 0; src < 8; ++src) wv += s.wrecv[src][tid];
            s.wsm[tid] = wv;
        }
        __syncthreads();
        // ---- attention e for MY batch ----
        {
            float a[4] = {0, 0, 0, 0};
            const float* uxp = g_UXt + ((size_t)gb * T_ + e_uq * 16) * N_ + e_ng * 4;
#pragma unroll 4
            for (int uu = 0; uu < 16; ++uu) {
                int u = e_uq * 16 + uu;
                float wv = s.wsm[u], vv = s.vds[u];
                float4 x4 = *(const float4*)(uxp + (size_t)uu * N_);
                a[0] = fmaf(tanha_(wv + x4.x), vv, a[0]);
                a[1] = fmaf(tanha_(wv + x4.y), vv, a[1]);
                a[2] = fmaf(tanha_(wv + x4.z), vv, a[2]);
                a[3] = fmaf(tanha_(wv + x4.w), vv, a[3]);
            }
            *(float4*)&s.epart[e_uq][e_ng * 4] = make_float4(a[0], a[1], a[2], a[3]);
        }
        __syncthreads();
        // ---- softmax over n + output ----
        float e = 0.f, p = 0.f;
        if (tid < 128) {
#pragma unroll
            for (int uq = 0; uq < 8; ++uq) e += s.epart[uq][tid];
            float mx = e;
#pragma unroll
            for (int o = 16; o; o >>= 1)
                mx = fmaxf(mx, __shfl_xor_sync(0xffffffffu, mx, o));
            if ((tid & 31) == 0) s.redm[tid >> 5] = mx;
        }
        __syncthreads();
        if (tid < 128) {
            float mx = fmaxf(fmaxf(s.redm[0], s.redm[1]), fmaxf(s.redm[2], s.redm[3]));
            p = __expf(e - mx);
            float sum = p;
#pragma unroll
            for (int o = 16; o; o >>= 1)
                sum += __shfl_xor_sync(0xffffffffu, sum, o);
            if ((tid & 31) == 0) s.reds[tid >> 5] = sum;
        }
        __syncthreads();
        if (tid < 128) {
            float tot = s.reds[0] + s.reds[1] + s.reds[2] + s.reds[3];
            size_t idx = ((size_t)gb * T_ + t) * N_ + tid;
            out[idx] = X[idx] * __fdividef(p, tot);
        }
        // cross-iteration hazards are all separated by cluster sync #1 of the
        // next iteration (peer-visible buffers) or local __syncthreads (local).
    }
}

// ---------------------------------------------------------------------------
// Inputs: X, h0, s0, Wx, Wh, b, Wd, bW, Ud, bU, vd, bv (bv cancels in softmax)
// ---------------------------------------------------------------------------
extern "C" void kernel_launch(void* const* d_in, const int* in_sizes, int n_in,
                              void* d_out, int out_size) {
    const float* X  = (const float*)d_in[0];
    const float* h0 = (const float*)d_in[1];
    const float* s0 = (const float*)d_in[2];
    const float* Wx = (const float*)d_in[3];
    const float* Wh = (const float*)d_in[4];
    const float* bz = (const float*)d_in[5];
    const float* Wd = (const float*)d_in[6];
    const float* bW = (const float*)d_in[7];
    const float* Ud = (const float*)d_in[8];
    const float* bU = (const float*)d_in[9];
    const float* vd = (const float*)d_in[10];
    float* out = (float*)d_out;

    cudaFuncSetAttribute(darnn_main, cudaFuncAttributeMaxDynamicSharedMemorySize,
                         (int)sizeof(SM));

    dim3 g1(FourM / 64, (B_ * T_) / 64);
    xwx_gemm<<<g1, 256>>>(X, Wx, bz);
    uxt_kernel<<<B_, 256>>>(X, Ud, bU);
    darnn_main<<<B_, 256, sizeof(SM)>>>(X, h0, s0, Wh, Wd, bW, vd, out);
}

// round 5
// speedup vs baseline: 2.2753x; 1.7262x over previous
#include <cuda_runtime.h>
#include <cstdint>

#define B_    128
#define T_    128
#define N_    128
#define M_    256
#define FourM 1024
#define RANKS 8
#define MB    8

__device__ float g_XWx[(size_t)B_ * T_ * FourM];   // [b*T + t][j] : x@Wx + b
__device__ float g_UXt[(size_t)B_ * T_ * N_];      // [b][u][n]    : U(X^T) + bU

__device__ __forceinline__ float sigmoid_(float x) {
    return __fdividef(1.f, 1.f + __expf(-x));
}
__device__ __forceinline__ float tanh_(float x) {          // accurate (gates)
    float e = __expf(2.f * x);
    return 1.f - __fdividef(2.f, e + 1.f);
}
__device__ __forceinline__ float tanha_(float x) {         // fast (attention)
    float y;
    asm("tanh.approx.f32 %0, %1;" : "=f"(y) : "f"(x));
    return y;
}
__device__ __forceinline__ uint32_t smem_u32(const void* p) {
    return (uint32_t)__cvta_generic_to_shared(p);
}
__device__ __forceinline__ uint32_t mapa_rank(uint32_t a, uint32_t r) {
    uint32_t d;
    asm("mapa.shared::cluster.u32 %0, %1, %2;" : "=r"(d) : "r"(a), "r"(r));
    return d;
}
__device__ __forceinline__ void st_cluster4(uint32_t a, float4 v) {
    asm volatile("st.shared::cluster.v4.f32 [%0], {%1,%2,%3,%4};"
                 :: "r"(a), "f"(v.x), "f"(v.y), "f"(v.z), "f"(v.w) : "memory");
}
__device__ __forceinline__ void st_cluster2(uint32_t a, float x, float y) {
    asm volatile("st.shared::cluster.v2.f32 [%0], {%1,%2};"
                 :: "r"(a), "f"(x), "f"(y) : "memory");
}
__device__ __forceinline__ void cluster_sync_() {
    asm volatile("barrier.cluster.arrive.aligned;" ::: "memory");
    asm volatile("barrier.cluster.wait.aligned;" ::: "memory");
}
#define FMAX2(d, a, b, c) \
    asm("fma.rn.f32x2 %0, %1, %2, %3;" : "=l"(d) : "l"(a), "l"(b), "l"(c))

// ---------------------------------------------------------------------------
// Kernel 1: g_XWx = X @ Wx + b
// ---------------------------------------------------------------------------
__global__ void __launch_bounds__(256) xwx_gemm(const float* __restrict__ X,
                                                const float* __restrict__ Wx,
                                                const float* __restrict__ bias) {
    __shared__ float As[16][64];
    __shared__ float Bs[16][64];
    const int tid  = threadIdx.x;
    const int row0 = blockIdx.y * 64;
    const int col0 = blockIdx.x * 64;
    const int tx = tid & 15;
    const int ty = tid >> 4;
    const int am = tid >> 2;
    const int ak = (tid & 3) * 4;
    const int bk = tid >> 4;
    const int bj = (tid & 15) * 4;

    float acc[4][4];
#pragma unroll
    for (int i = 0; i < 4; i++)
#pragma unroll
        for (int j = 0; j < 4; j++) acc[i][j] = 0.f;

    for (int k0 = 0; k0 < 128; k0 += 16) {
        float4 av = *(const float4*)(X + (row0 + am) * 128 + k0 + ak);
        As[ak + 0][am] = av.x;
        As[ak + 1][am] = av.y;
        As[ak + 2][am] = av.z;
        As[ak + 3][am] = av.w;
        *(float4*)&Bs[bk][bj] = *(const float4*)(Wx + (k0 + bk) * FourM + col0 + bj);
        __syncthreads();
#pragma unroll
        for (int k = 0; k < 16; k++) {
            float4 a4 = *(const float4*)&As[k][ty * 4];
            float4 b4 = *(const float4*)&Bs[k][tx * 4];
            float a[4] = {a4.x, a4.y, a4.z, a4.w};
            float b[4] = {b4.x, b4.y, b4.z, b4.w};
#pragma unroll
            for (int i = 0; i < 4; i++)
#pragma unroll
                for (int j = 0; j < 4; j++) acc[i][j] = fmaf(a[i], b[j], acc[i][j]);
        }
        __syncthreads();
    }
    float4 b4 = *(const float4*)(bias + col0 + tx * 4);
    float bb[4] = {b4.x, b4.y, b4.z, b4.w};
#pragma unroll
    for (int i = 0; i < 4; i++) {
        float4 rr = make_float4(acc[i][0] + bb[0], acc[i][1] + bb[1],
                                acc[i][2] + bb[2], acc[i][3] + bb[3]);
        *(float4*)&g_XWx[(size_t)(row0 + ty * 4 + i) * FourM + col0 + tx * 4] = rr;
    }
}

// ---------------------------------------------------------------------------
// Kernel 2: g_UXt[b][u][n] = sum_t X[b][t][n]*Ud[t][u] + bU[u]
// ---------------------------------------------------------------------------
__global__ void __launch_bounds__(256) uxt_kernel(const float* __restrict__ X,
                                                  const float* __restrict__ Ud,
                                                  const float* __restrict__ bU) {
    __shared__ float Xs[32][128];
    __shared__ float Us[32][128];
    const int b   = blockIdx.x;
    const int tid = threadIdx.x;
    const int n   = tid & 127;
    const int uh  = tid >> 7;

    float acc[64];
#pragma unroll
    for (int i = 0; i < 64; ++i) acc[i] = 0.f;

    for (int t0 = 0; t0 < 128; t0 += 32) {
        for (int l = tid; l < 32 * 128; l += 256) {
            int tt = l >> 7, nn = l & 127;
            Xs[tt][nn] = X[(b * 128 + t0 + tt) * 128 + nn];
            Us[tt][nn] = Ud[(t0 + tt) * 128 + nn];
        }
        __syncthreads();
#pragma unroll 2
        for (int tt = 0; tt < 32; ++tt) {
            float xv = Xs[tt][n];
            const float* up = &Us[tt][uh * 64];
#pragma unroll
            for (int uu = 0; uu < 64; ++uu) acc[uu] = fmaf(xv, up[uu], acc[uu]);
        }
        __syncthreads();
    }
#pragma unroll 4
    for (int uu = 0; uu < 64; ++uu) {
        int u = uh * 64 + uu;
        g_UXt[(size_t)(b * 128 + u) * 128 + n] = acc[uu] + bU[u];
    }
}

// ---------------------------------------------------------------------------
// Kernel 3: 16 clusters x 8 CTAs x 512 threads. Wh/Wd register-resident,
// f32x2 packed FMA, duplicated-h smem (conflict-free broadcasts).
// ---------------------------------------------------------------------------
struct SM {
    float h_dup[8][512];        // h duplicated: [b][2m]=[b][2m+1]=h[m]   16KB
    float zbuf[8][8][64][2];    // p1 partials [q][b][colpair][2]         32KB
    float zfull[8][128];        // z for local 128 cols                    4KB
    float hs_own[8][68];        // [b][0:32)=h slice,[32:64)=c (padded)   2.2KB
    float c_loc[8][32];         // persistent c for own m-slice            1KB
    float wloc[16][8][128];     // p2 partials [kq][b][u]                 64KB
    float wrecv[8][128];        // w partials from each src rank           4KB
    float wsm[128];
    float epart[16][128];       //                                         8KB
    float vds[128];
    float bWs[128];
    float redm[4];
    float reds[4];
};

__global__ void __launch_bounds__(512, 1) __cluster_dims__(RANKS, 1, 1)
darnn_main(const float* __restrict__ X, const float* __restrict__ h0,
           const float* __restrict__ s0, const float* __restrict__ Wh,
           const float* __restrict__ Wd, const float* __restrict__ bW,
           const float* __restrict__ vd, float* __restrict__ out) {
    extern __shared__ char smraw[];
    SM& s = *reinterpret_cast<SM*>(smraw);
    const int tid = threadIdx.x;
    const int r   = blockIdx.x & 7;
    const int b0  = (blockIdx.x >> 3) * MB;
    const int gb  = b0 + r;

    // ---- persistent register weights ----
    // p1: thread (q = tid>>6, cg = tid&63) owns Wh rows q*32..+32, col pair
    //     local j = {cg*2, cg*2+1}; global col = (cg>>4)*256 + r*32 + (cg*2 & 31)
    const int q   = tid >> 6;
    const int cg  = tid & 63;
    const int gC  = (cg >> 4) * 256 + r * 32 + ((cg * 2) & 31);
    unsigned long long Wp[32];
#pragma unroll
    for (int kk = 0; kk < 32; ++kk) {
        float2 w2 = *(const float2*)(Wh + (size_t)(q * 32 + kk) * FourM + gC);
        asm("mov.b64 %0, {%1, %2};" : "=l"(Wp[kk]) : "f"(w2.x), "f"(w2.y));
    }
    // p2: thread (uq = tid&31, kq = tid>>5) owns Wd rows (4 of own k-slice) x 4 u
    const int p2_uq = tid & 31;
    const int p2_kq = tid >> 5;    // 0..15 -> local k index kq*4..+4 in [0,64)
    float4 Wq[4];
#pragma unroll
    for (int i = 0; i < 4; ++i) {
        int kl = p2_kq * 4 + i;
        int gk = (kl < 32) ? (r * 32 + kl) : (256 + r * 32 + (kl - 32));
        Wq[i] = *(const float4*)(Wd + (size_t)gk * T_ + p2_uq * 4);
    }

    // ---- prologue: state + small vectors ----
    for (int fid = tid; fid < 8 * 256; fid += 512) {
        int b = fid >> 8, m = fid & 255;
        float v = h0[(size_t)(b0 + b) * M_ + m];
        s.h_dup[b][2 * m]     = v;
        s.h_dup[b][2 * m + 1] = v;
    }
    if (tid < 256) {
        int b = tid >> 5, mi = tid & 31;
        s.c_loc[b][mi] = s0[(size_t)(b0 + b) * M_ + r * 32 + mi];
    }
    if (tid < 128) { s.vds[tid] = vd[tid]; s.bWs[tid] = bW[tid]; }
    __syncthreads();

    // other thread mappings
    const int x_b  = tid >> 6;       // prefetch/reduce batch
    const int x_j2 = tid & 63;       // prefetch/reduce col pair
    const int x_gC = (x_j2 >> 4) * 256 + r * 32 + ((x_j2 * 2) & 31);
    const int g_rb = tid >> 5;       // gates b (tid<256)
    const int g_rq = tid & 31;       // gates mi
    const int h_bb = tid >> 4;       // broadcast b (tid<128)
    const int h_qm = tid & 15;       // broadcast h pair
    const int e_uq = tid >> 5;       // p3 u-range (8 u)
    const int e_ng = tid & 31;       // p3 n-quad

    for (int t = 0; t < T_; ++t) {
        // prefetch XWx contribution for (x_b, cols x_j2*2..+1)
        float2 xw2 = *(const float2*)(g_XWx + ((size_t)(b0 + x_b) * T_ + t) * FourM + x_gC);

        // ---- phase 1: z-partials, packed f32x2, register weights ----
        {
            const float* hd = s.h_dup[0] + q * 64;   // b advances by 512 floats
#pragma unroll 1
            for (int b = 0; b < 8; ++b) {
                unsigned long long acc = 0ULL;
#pragma unroll
                for (int kk = 0; kk < 32; kk += 2) {
                    ulonglong2 hh = *(const ulonglong2*)(hd + b * 512 + 2 * kk);
                    FMAX2(acc, Wp[kk], hh.x, acc);
                    FMAX2(acc, Wp[kk + 1], hh.y, acc);
                }
                float z0, z1;
                asm("mov.b64 {%0, %1}, %2;" : "=f"(z0), "=f"(z1) : "l"(acc));
                *(float2*)&s.zbuf[q][b][cg][0] = make_float2(z0, z1);
            }
        }
        cluster_sync_();   // #1: peers done reading h_dup; zbuf visible

        // ---- z reduce: zfull[b][j] = xw + sum_q zbuf ----
        {
            float s0_ = xw2.x, s1_ = xw2.y;
#pragma unroll
            for (int qq = 0; qq < 8; ++qq) {
                float2 p = *(const float2*)&s.zbuf[qq][x_b][x_j2][0];
                s0_ += p.x;
                s1_ += p.y;
            }
            *(float2*)&s.zfull[x_b][x_j2 * 2] = make_float2(s0_, s1_);
        }
        __syncthreads();
        // ---- gates for own m-slice ----
        if (tid < 256) {
            float ig = sigmoid_(s.zfull[g_rb][g_rq]);
            float fg = sigmoid_(s.zfull[g_rb][32 + g_rq]);
            float gg = tanh_(s.zfull[g_rb][64 + g_rq]);
            float og = sigmoid_(s.zfull[g_rb][96 + g_rq]);
            float c  = fmaf(fg, s.c_loc[g_rb][g_rq], ig * gg);
            float h  = og * tanh_(c);
            s.c_loc[g_rb][g_rq]       = c;
            s.hs_own[g_rb][g_rq]      = h;
            s.hs_own[g_rb][32 + g_rq] = c;
        }
        __syncthreads();
        // ---- h broadcast (duplicated) to all ranks ----
        if (tid < 128) {
            float hx = s.hs_own[h_bb][h_qm * 2];
            float hy = s.hs_own[h_bb][h_qm * 2 + 1];
            float4 d4 = make_float4(hx, hx, hy, hy);
            uint32_t la = smem_u32(&s.h_dup[h_bb][r * 64 + h_qm * 4]);
#pragma unroll
            for (int d = 0; d < 8; ++d) st_cluster4(mapa_rank(la, d), d4);
        }
        // ---- phase 2: w partials (register Wd, uniform h loads) ----
        {
#pragma unroll 1
            for (int b = 0; b < 8; ++b) {
                float a0 = 0, a1 = 0, a2 = 0, a3 = 0;
#pragma unroll
                for (int i = 0; i < 4; ++i) {
                    float hv = s.hs_own[b][p2_kq * 4 + i];
                    a0 = fmaf(hv, Wq[i].x, a0);
                    a1 = fmaf(hv, Wq[i].y, a1);
                    a2 = fmaf(hv, Wq[i].z, a2);
                    a3 = fmaf(hv, Wq[i].w, a3);
                }
                *(float4*)&s.wloc[p2_kq][b][p2_uq * 4] = make_float4(a0, a1, a2, a3);
            }
        }
        __syncthreads();
        // ---- local kq-reduce + push to batch owner ----
        {
            float s0_ = 0, s1_ = 0;
#pragma unroll
            for (int kq = 0; kq < 16; ++kq) {
                float2 p = *(const float2*)&s.wloc[kq][x_b][x_j2 * 2];
                s0_ += p.x;
                s1_ += p.y;
            }
            uint32_t la = smem_u32(&s.wrecv[r][x_j2 * 2]);
            st_cluster2(mapa_rank(la, x_b), s0_, s1_);
        }
        cluster_sync_();   // #2: h_dup updated + w partials delivered

        // ---- combine w ----
        if (tid < 128) {
            float wv = s.bWs[tid];
#pragma unroll
            for (int src = 0; src < 8; ++src) wv += s.wrecv[src][tid];
            s.wsm[tid] = wv;
        }
        __syncthreads();
        // ---- phase 3: attention e for MY batch ----
        {
            float a0 = 0, a1 = 0, a2 = 0, a3 = 0;
            const float* uxp = g_UXt + ((size_t)gb * T_ + e_uq * 8) * N_ + e_ng * 4;
#pragma unroll
            for (int uu = 0; uu < 8; ++uu) {
                int u = e_uq * 8 + uu;
                float wv = s.wsm[u], vv = s.vds[u];
                float4 x4 = *(const float4*)(uxp + (size_t)uu * N_);
                a0 = fmaf(tanha_(wv + x4.x), vv, a0);
                a1 = fmaf(tanha_(wv + x4.y), vv, a1);
                a2 = fmaf(tanha_(wv + x4.z), vv, a2);
                a3 = fmaf(tanha_(wv + x4.w), vv, a3);
            }
            *(float4*)&s.epart[e_uq][e_ng * 4] = make_float4(a0, a1, a2, a3);
        }
        __syncthreads();
        // ---- softmax over n + output ----
        float e = 0.f, p = 0.f;
        if (tid < 128) {
#pragma unroll
            for (int uq = 0; uq < 16; ++uq) e += s.epart[uq][tid];
            float mx = e;
#pragma unroll
            for (int o = 16; o; o >>= 1)
                mx = fmaxf(mx, __shfl_xor_sync(0xffffffffu, mx, o));
            if ((tid & 31) == 0) s.redm[tid >> 5] = mx;
        }
        __syncthreads();
        if (tid < 128) {
            float mx = fmaxf(fmaxf(s.redm[0], s.redm[1]), fmaxf(s.redm[2], s.redm[3]));
            p = __expf(e - mx);
            float sum = p;
#pragma unroll
            for (int o = 16; o; o >>= 1)
                sum += __shfl_xor_sync(0xffffffffu, sum, o);
            if ((tid & 31) == 0) s.reds[tid >> 5] = sum;
        }
        __syncthreads();
        if (tid < 128) {
            float tot = s.reds[0] + s.reds[1] + s.reds[2] + s.reds[3];
            size_t idx = ((size_t)gb * T_ + t) * N_ + tid;
            out[idx] = X[idx] * __fdividef(p, tot);
        }
        // cross-CTA buffers (h_dup, wrecv) are only rewritten after the next
        // step's cluster_sync #1, which follows every reader above.
    }
}

// ---------------------------------------------------------------------------
// Inputs: X, h0, s0, Wx, Wh, b, Wd, bW, Ud, bU, vd, bv (bv cancels in softmax)
// ---------------------------------------------------------------------------
extern "C" void kernel_launch(void* const* d_in, const int* in_sizes, int n_in,
                              void* d_out, int out_size) {
    const float* X  = (const float*)d_in[0];
    const float* h0 = (const float*)d_in[1];
    const float* s0 = (const float*)d_in[2];
    const float* Wx = (const float*)d_in[3];
    const float* Wh = (const float*)d_in[4];
    const float* bz = (const float*)d_in[5];
    const float* Wd = (const float*)d_in[6];
    const float* bW = (const float*)d_in[7];
    const float* Ud = (const float*)d_in[8];
    const float* bU = (const float*)d_in[9];
    const float* vd = (const float*)d_in[10];
    float* out = (float*)d_out;

    cudaFuncSetAttribute(darnn_main, cudaFuncAttributeMaxDynamicSharedMemorySize,
                         (int)sizeof(SM));

    dim3 g1(FourM / 64, (B_ * T_) / 64);
    xwx_gemm<<<g1, 256>>>(X, Wx, bz);
    uxt_kernel<<<B_, 256>>>(X, Ud, bU);
    darnn_main<<<B_, 512, sizeof(SM)>>>(X, h0, s0, Wh, Wd, bW, vd, out);
}